// round 1
// baseline (speedup 1.0000x reference)
#include <cuda_runtime.h>
#include <cuda_bf16.h>

#define DIM      64
#define NEMB     1024
#define TC       64          // codes per shared tile
#define BLK      256         // threads per block (1 row per thread)
#define EPSF     1e-5f

// ---------------- device scratch (no allocations allowed) ----------------
__device__ float g_enorm[NEMB];        // ||e_c||^2
__device__ float g_onehot[NEMB];       // counts per code
__device__ float g_esum[DIM * NEMB];   // sum of f per code, [dim][n_embed]
__device__ float g_diffsum;            // sum over rows of ||q - x||^2

// ---------------- kernel 0: zero scratch + precompute code norms ---------
__global__ void vq_init(const float* __restrict__ embed) {
    int i = blockIdx.x * blockDim.x + threadIdx.x;
    if (i < DIM * NEMB) g_esum[i] = 0.f;
    if (i < NEMB) {
        g_onehot[i] = 0.f;
        float s = 0.f;
#pragma unroll
        for (int d = 0; d < DIM; ++d) {
            float v = embed[d * NEMB + i];
            s = fmaf(v, v, s);
        }
        g_enorm[i] = s;
    }
    if (i == 0) g_diffsum = 0.f;
}

// ---------------- kernel 1: argmin search + gather + stats ---------------
__global__ __launch_bounds__(BLK, 2)
void vq_main(const float* __restrict__ x, const float* __restrict__ embed,
             float* __restrict__ out_q, float* __restrict__ out_ind) {
    __shared__ float sE[TC][DIM + 4];   // pad 4 floats: keeps float4 alignment, spreads STS banks
    __shared__ float sN[TC];
    __shared__ float sRed[BLK];

    const int tid = threadIdx.x;
    const int r   = blockIdx.x * BLK + tid;

    // load this row's feature vector into registers (16x float4, coalesced per-lane segments)
    float f[DIM];
    {
        const float4* xr = reinterpret_cast<const float4*>(x + (size_t)r * DIM);
#pragma unroll
        for (int i = 0; i < DIM / 4; ++i) {
            float4 v = xr[i];
            f[4 * i + 0] = v.x; f[4 * i + 1] = v.y;
            f[4 * i + 2] = v.z; f[4 * i + 3] = v.w;
        }
    }
    float fn = 0.f;
#pragma unroll
    for (int d = 0; d < DIM; ++d) fn = fmaf(f[d], f[d], fn);

    float best = 3.4e38f;
    int   bidx = 0;

    for (int cb = 0; cb < NEMB; cb += TC) {
        // cooperative transpose load: sE[c][d] = embed[d][cb+c]; global reads coalesced over c
#pragma unroll
        for (int i = tid; i < TC * DIM; i += BLK) {
            int c = i & (TC - 1);
            int d = i >> 6;             // TC == 64
            sE[c][d] = embed[d * NEMB + cb + c];
        }
        if (tid < TC) sN[tid] = g_enorm[cb + tid];
        __syncthreads();

#pragma unroll 4
        for (int c = 0; c < TC; ++c) {
            const float* e = &sE[c][0];
            float a0 = 0.f, a1 = 0.f, a2 = 0.f, a3 = 0.f;
#pragma unroll
            for (int d = 0; d < DIM; d += 8) {
                float4 v0 = *reinterpret_cast<const float4*>(e + d);       // broadcast LDS.128
                float4 v1 = *reinterpret_cast<const float4*>(e + d + 4);
                a0 = fmaf(f[d + 0], v0.x, a0);
                a1 = fmaf(f[d + 1], v0.y, a1);
                a2 = fmaf(f[d + 2], v0.z, a2);
                a3 = fmaf(f[d + 3], v0.w, a3);
                a0 = fmaf(f[d + 4], v1.x, a0);
                a1 = fmaf(f[d + 5], v1.y, a1);
                a2 = fmaf(f[d + 6], v1.z, a2);
                a3 = fmaf(f[d + 7], v1.w, a3);
            }
            float score = sN[c] - 2.f * ((a0 + a1) + (a2 + a3));  // ||e||^2 - 2 f.e
            if (score < best) { best = score; bidx = cb + c; }    // strict <: first-min tie rule
        }
        __syncthreads();
    }

    // ---- epilogue ----
    out_ind[r] = (float)bidx;

    // quantize gather (embed fits in L2) + write; EMA stat atomics
    const float* ecol = embed + bidx;
    float* qdst = out_q + (size_t)r * DIM;
#pragma unroll
    for (int d = 0; d < DIM; ++d) {
        qdst[d] = ecol[(size_t)d * NEMB];
        atomicAdd(&g_esum[d * NEMB + bidx], f[d]);
    }
    atomicAdd(&g_onehot[bidx], 1.0f);

    // ||q - x||^2 == ||f||^2 + score_min  (algebraic identity)
    float diffp = fn + best;
    sRed[tid] = diffp;
    __syncthreads();
#pragma unroll
    for (int s = BLK / 2; s > 0; s >>= 1) {
        if (tid < s) sRed[tid] += sRed[tid + s];
        __syncthreads();
    }
    if (tid == 0) atomicAdd(&g_diffsum, sRed[0]);
}

// ---------------- kernel 2: EMA finalize + scalar loss -------------------
__global__ void vq_fin(const float* __restrict__ cs, const float* __restrict__ ea,
                       float* __restrict__ out_diff, float* __restrict__ out_ncs,
                       float* __restrict__ out_nea, float* __restrict__ out_ne,
                       int nrows) {
    __shared__ float red[NEMB];
    const int t = threadIdx.x;

    float ncs = 0.99f * cs[t] + 0.01f * g_onehot[t];
    out_ncs[t] = ncs;

    red[t] = ncs;
    __syncthreads();
#pragma unroll
    for (int s = NEMB / 2; s > 0; s >>= 1) {
        if (t < s) red[t] += red[t + s];
        __syncthreads();
    }
    float n = red[0];
    float csn = (ncs + EPSF) / (n + (float)(NEMB) * EPSF) * n;

#pragma unroll
    for (int d = 0; d < DIM; ++d) {
        int i = d * NEMB + t;
        float nea = 0.99f * ea[i] + 0.01f * g_esum[i];
        out_nea[i] = nea;
        out_ne[i]  = nea / csn;
    }
    if (t == 0) out_diff[0] = g_diffsum / (float)((size_t)nrows * DIM);
}

// ---------------- launch ----------------
extern "C" void kernel_launch(void* const* d_in, const int* in_sizes, int n_in,
                              void* d_out, int out_size) {
    const float* x     = (const float*)d_in[0];   // [32,64,64,64]
    const float* embed = (const float*)d_in[1];   // [64,1024]
    const float* cs    = (const float*)d_in[2];   // [1024]
    const float* ea    = (const float*)d_in[3];   // [64,1024]
    float* out = (float*)d_out;

    const int xsz = in_sizes[0];       // 8388608
    const int N   = xsz / DIM;         // 131072 rows

    // output packing: quantize_st | diff | embed_ind | new_cluster_size | new_embed_avg | new_embed
    float* out_q    = out;
    float* out_diff = out + xsz;
    float* out_ind  = out_diff + 1;
    float* out_ncs  = out_ind + N;
    float* out_nea  = out_ncs + NEMB;
    float* out_ne   = out_nea + DIM * NEMB;

    vq_init<<<(DIM * NEMB + 255) / 256, 256>>>(embed);
    vq_main<<<N / BLK, BLK>>>(x, embed, out_q, out_ind);
    vq_fin<<<1, NEMB>>>(cs, ea, out_diff, out_ncs, out_nea, out_ne, N);
}

// round 3
// speedup vs baseline: 2.2113x; 2.2113x over previous
#include <cuda_runtime.h>
#include <cuda_fp16.h>
#include <cstdint>

#define DIM      64
#define NEMB     1024
#define NROWS    131072
#define MTILE    128
#define NCH      64           // codes per chunk
#define NCHUNKS  (NEMB / NCH)
#define BROW     72           // padded B smem row stride in halves (16B-aligned, conflict-free)
#define EPSF     1e-5f

// ---------------- device scratch (static, no allocation) ----------------
__device__ __half g_xhi[NROWS * DIM];
__device__ __half g_xlo[NROWS * DIM];
__device__ __half g_eThi[NEMB * DIM];    // embed^T hi, [code][dim]
__device__ __half g_eTlo[NEMB * DIM];
__device__ float  g_eTf [NEMB * DIM];    // embed^T fp32 (gather + rescore)
__device__ float  g_enorm[NEMB];
__device__ float  g_onehot[NEMB];
__device__ float  g_esum[DIM * NEMB];
__device__ float  g_diffsum;

// ---------------- PTX helpers ----------------
__device__ __forceinline__ uint32_t smem_u32(const void* p) {
    uint32_t a;
    asm("{ .reg .u64 t; cvta.to.shared.u64 t, %1; cvt.u32.u64 %0, t; }" : "=r"(a) : "l"(p));
    return a;
}
__device__ __forceinline__ void mma16816(float* d, const uint32_t* a, uint32_t b0, uint32_t b1) {
    asm volatile(
        "mma.sync.aligned.m16n8k16.row.col.f32.f16.f16.f32 "
        "{%0,%1,%2,%3}, {%4,%5,%6,%7}, {%8,%9}, {%0,%1,%2,%3};"
        : "+f"(d[0]), "+f"(d[1]), "+f"(d[2]), "+f"(d[3])
        : "r"(a[0]), "r"(a[1]), "r"(a[2]), "r"(a[3]), "r"(b0), "r"(b1));
}
#define CP16(dst, src) asm volatile("cp.async.cg.shared.global [%0], [%1], 16;" :: "r"(dst), "l"(src) : "memory")
#define CP_COMMIT()    asm volatile("cp.async.commit_group;" ::: "memory")
#define CP_WAIT(n)     asm volatile("cp.async.wait_group %0;" :: "n"(n) : "memory")

// ---------------- pre-pass: split x into fp16 hi/lo ----------------
__global__ void vq_split(const float* __restrict__ x) {
    size_t i = ((size_t)blockIdx.x * blockDim.x + threadIdx.x) * 4;
    float4 v = *reinterpret_cast<const float4*>(x + i);
    __half h0 = __float2half_rn(v.x), h1 = __float2half_rn(v.y);
    __half h2 = __float2half_rn(v.z), h3 = __float2half_rn(v.w);
    __half l0 = __float2half_rn(v.x - __half2float(h0));
    __half l1 = __float2half_rn(v.y - __half2float(h1));
    __half l2 = __float2half_rn(v.z - __half2float(h2));
    __half l3 = __float2half_rn(v.w - __half2float(h3));
    *reinterpret_cast<__half2*>(g_xhi + i)     = __halves2half2(h0, h1);
    *reinterpret_cast<__half2*>(g_xhi + i + 2) = __halves2half2(h2, h3);
    *reinterpret_cast<__half2*>(g_xlo + i)     = __halves2half2(l0, l1);
    *reinterpret_cast<__half2*>(g_xlo + i + 2) = __halves2half2(l2, l3);
}

// ---------------- pre-pass: embed transpose/split + norms + zero stats ---
__global__ void vq_prep(const float* __restrict__ embed) {
    int i = blockIdx.x * blockDim.x + threadIdx.x;   // 65536 threads
    int d = i >> 10, n = i & (NEMB - 1);
    float e = embed[i];
    int t = n * DIM + d;
    g_eTf[t] = e;
    __half h = __float2half_rn(e);
    g_eThi[t] = h;
    g_eTlo[t] = __float2half_rn(e - __half2float(h));
    g_esum[i] = 0.f;
    if (i < NEMB) {
        g_onehot[i] = 0.f;
        float s = 0.f;
#pragma unroll
        for (int dd = 0; dd < DIM; ++dd) {
            float v = embed[dd * NEMB + i];
            s = fmaf(v, v, s);
        }
        g_enorm[i] = s;
    }
    if (i == 0) g_diffsum = 0.f;
}

// ---------------- main kernel ----------------
__global__ __launch_bounds__(128)
void vq_main(const float* __restrict__ x, float* __restrict__ out_q,
             float* __restrict__ out_ind) {
    __shared__ __half sB[2][2][NCH * BROW];   // [buf][hi/lo] : 4*9216B = 36864B
    __shared__ float sEn[NEMB];               // 4KB

    const int tid  = threadIdx.x;
    const int warp = tid >> 5;
    const int lane = tid & 31;
    const int g    = lane >> 2;       // 0..7
    const int q    = lane & 3;        // 0..3
    const int row0 = blockIdx.x * MTILE;

#pragma unroll
    for (int i = tid; i < NEMB; i += 128) sEn[i] = g_enorm[i];

    // ---- stage A rows into sB region (temporary), extract register frags ----
    __half* sA = &sB[0][0][0];        // uses 16384 halves of the 18432 available
    {
        const uint4* shi = reinterpret_cast<const uint4*>(g_xhi + (size_t)row0 * DIM);
        const uint4* slo = reinterpret_cast<const uint4*>(g_xlo + (size_t)row0 * DIM);
        uint4* dhi = reinterpret_cast<uint4*>(sA);
        uint4* dlo = reinterpret_cast<uint4*>(sA + MTILE * DIM);
#pragma unroll
        for (int i = tid; i < MTILE * DIM / 8; i += 128) {   // 1024 uint4 each
            dhi[i] = shi[i];
            dlo[i] = slo[i];
        }
    }
    __syncthreads();

    uint32_t Ah[2][4][4], Al[2][4][4];
    {
        const __half* sAl = sA + MTILE * DIM;
        const int c0 = q * 2;
#pragma unroll
        for (int mt = 0; mt < 2; ++mt) {
            const int ra = warp * 32 + mt * 16 + g;
            const int rb = ra + 8;
#pragma unroll
            for (int k = 0; k < 4; ++k) {
                const int cc = k * 16 + c0;
                Ah[mt][k][0] = *reinterpret_cast<const uint32_t*>(sA  + ra * DIM + cc);
                Ah[mt][k][1] = *reinterpret_cast<const uint32_t*>(sA  + rb * DIM + cc);
                Ah[mt][k][2] = *reinterpret_cast<const uint32_t*>(sA  + ra * DIM + cc + 8);
                Ah[mt][k][3] = *reinterpret_cast<const uint32_t*>(sA  + rb * DIM + cc + 8);
                Al[mt][k][0] = *reinterpret_cast<const uint32_t*>(sAl + ra * DIM + cc);
                Al[mt][k][1] = *reinterpret_cast<const uint32_t*>(sAl + rb * DIM + cc);
                Al[mt][k][2] = *reinterpret_cast<const uint32_t*>(sAl + ra * DIM + cc + 8);
                Al[mt][k][3] = *reinterpret_cast<const uint32_t*>(sAl + rb * DIM + cc + 8);
            }
        }
    }
    __syncthreads();   // staging region free for B buffers now

    // ---- B chunk prefetch pipeline (cp.async, double buffered) ----
    auto load_chunk = [&](int buf, int cb) {
#pragma unroll
        for (int i = tid; i < NCH * 8; i += 128) {     // 512 16B segs per matrix
            int row = i >> 3, seg = i & 7;
            CP16(smem_u32(&sB[buf][0][row * BROW + seg * 8]),
                 g_eThi + (size_t)(cb + row) * DIM + seg * 8);
            CP16(smem_u32(&sB[buf][1][row * BROW + seg * 8]),
                 g_eTlo + (size_t)(cb + row) * DIM + seg * 8);
        }
    };

    float b1s[4], b2s[4];
    int   b1i[4], b2i[4];
#pragma unroll
    for (int rr = 0; rr < 4; ++rr) { b1s[rr] = b2s[rr] = 3.4e38f; b1i[rr] = b2i[rr] = 0; }

    load_chunk(0, 0);
    CP_COMMIT();

    for (int c = 0; c < NCHUNKS; ++c) {
        if (c < NCHUNKS - 1) {
            load_chunk((c + 1) & 1, (c + 1) * NCH);
            CP_COMMIT();
            CP_WAIT(1);
        } else {
            CP_WAIT(0);
        }
        __syncthreads();

        float acc[2][8][4];
#pragma unroll
        for (int mt = 0; mt < 2; ++mt)
#pragma unroll
            for (int n = 0; n < 8; ++n)
#pragma unroll
                for (int v = 0; v < 4; ++v) acc[mt][n][v] = 0.f;

        const __half* Bh = sB[c & 1][0];
        const __half* Bl = sB[c & 1][1];

#pragma unroll
        for (int pass = 0; pass < 3; ++pass) {
            const uint32_t (*A)[4][4] = (pass == 2) ? Al : Ah;
            const __half* B = (pass == 1) ? Bl : Bh;
#pragma unroll
            for (int k = 0; k < 4; ++k) {
                uint32_t bf0[8], bf1[8];
#pragma unroll
                for (int n = 0; n < 8; ++n) {
                    const __half* p = B + (n * 8 + g) * BROW + k * 16 + q * 2;
                    bf0[n] = *reinterpret_cast<const uint32_t*>(p);
                    bf1[n] = *reinterpret_cast<const uint32_t*>(p + 8);
                }
#pragma unroll
                for (int mt = 0; mt < 2; ++mt)
#pragma unroll
                    for (int n = 0; n < 8; ++n)
                        mma16816(acc[mt][n], A[mt][k], bf0[n], bf1[n]);
            }
        }

        // ---- scoring + per-thread top-2 ----
        const int cb = c * NCH;
#pragma unroll
        for (int n = 0; n < 8; ++n) {
            const int code0 = cb + n * 8 + q * 2;
            const float en0 = sEn[code0], en1 = sEn[code0 + 1];
#pragma unroll
            for (int mt = 0; mt < 2; ++mt) {
#pragma unroll
                for (int h = 0; h < 2; ++h) {
                    const int rr = mt * 2 + h;
                    float s0 = fmaf(-2.f, acc[mt][n][h * 2],     en0);
                    float s1 = fmaf(-2.f, acc[mt][n][h * 2 + 1], en1);
                    if (s0 < b1s[rr]) { b2s[rr] = b1s[rr]; b2i[rr] = b1i[rr]; b1s[rr] = s0; b1i[rr] = code0; }
                    else if (s0 < b2s[rr]) { b2s[rr] = s0; b2i[rr] = code0; }
                    if (s1 < b1s[rr]) { b2s[rr] = b1s[rr]; b2i[rr] = b1i[rr]; b1s[rr] = s1; b1i[rr] = code0 + 1; }
                    else if (s1 < b2s[rr]) { b2s[rr] = s1; b2i[rr] = code0 + 1; }
                }
            }
        }
        __syncthreads();   // compute done before next iter overwrites this buffer
    }

    // ---- cross-lane top-2 merge (4 lanes per row group) ----
#pragma unroll
    for (int off = 1; off <= 2; off <<= 1) {
#pragma unroll
        for (int rr = 0; rr < 4; ++rr) {
            float o1s = __shfl_xor_sync(0xffffffffu, b1s[rr], off);
            int   o1i = __shfl_xor_sync(0xffffffffu, b1i[rr], off);
            float o2s = __shfl_xor_sync(0xffffffffu, b2s[rr], off);
            int   o2i = __shfl_xor_sync(0xffffffffu, b2i[rr], off);
            bool ob = (o1s < b1s[rr]) || (o1s == b1s[rr] && o1i < b1i[rr]);
            float n1s, n2s; int n1i, n2i;
            if (ob) {
                n1s = o1s; n1i = o1i;
                if (b1s[rr] < o2s || (b1s[rr] == o2s && b1i[rr] < o2i)) { n2s = b1s[rr]; n2i = b1i[rr]; }
                else                                                    { n2s = o2s;     n2i = o2i; }
            } else {
                n1s = b1s[rr]; n1i = b1i[rr];
                if (o1s < b2s[rr] || (o1s == b2s[rr] && o1i < b2i[rr])) { n2s = o1s;     n2i = o1i; }
                else                                                    { n2s = b2s[rr]; n2i = b2i[rr]; }
            }
            b1s[rr] = n1s; b1i[rr] = n1i; b2s[rr] = n2s; b2i[rr] = n2i;
        }
    }

    // ---- publish per-row candidates to smem (overlay on sB, all reads done) ----
    float* rs1 = reinterpret_cast<float*>(&sB[0][0][0]);
    int*   ri1 = reinterpret_cast<int*>(rs1 + MTILE);
    float* rs2 = rs1 + 2 * MTILE;
    int*   ri2 = reinterpret_cast<int*>(rs1 + 3 * MTILE);
    if (q == 0) {
#pragma unroll
        for (int rr = 0; rr < 4; ++rr) {
            int rl = warp * 32 + (rr >> 1) * 16 + (rr & 1) * 8 + g;
            rs1[rl] = b1s[rr]; ri1[rl] = b1i[rr];
            rs2[rl] = b2s[rr]; ri2[rl] = b2i[rr];
        }
    }
    __syncthreads();

    // ---- epilogue: one thread per row ----
    const int r = row0 + tid;
    float f[DIM];
    {
        const float4* xr = reinterpret_cast<const float4*>(x + (size_t)r * DIM);
#pragma unroll
        for (int j = 0; j < 16; ++j) {
            float4 v = xr[j];
            f[4 * j] = v.x; f[4 * j + 1] = v.y; f[4 * j + 2] = v.z; f[4 * j + 3] = v.w;
        }
    }
    int bidx = ri1[tid];
    // near-tie rescue: exact fp32 rescore of both candidates
    if (rs2[tid] - rs1[tid] < 5e-3f) {
        int i2 = ri2[tid];
        float d1 = 0.f, d2 = 0.f;
        const float* e1 = g_eTf + bidx * DIM;
        const float* e2 = g_eTf + i2 * DIM;
#pragma unroll
        for (int d = 0; d < DIM; ++d) {
            d1 = fmaf(f[d], e1[d], d1);
            d2 = fmaf(f[d], e2[d], d2);
        }
        float s1 = g_enorm[bidx] - 2.f * d1;
        float s2 = g_enorm[i2]   - 2.f * d2;
        if (s2 < s1 || (s2 == s1 && i2 < bidx)) bidx = i2;
    }
    out_ind[r] = (float)bidx;

    float dsum = 0.f;
    const float4* q4 = reinterpret_cast<const float4*>(g_eTf + bidx * DIM);
    float4* o4 = reinterpret_cast<float4*>(out_q + (size_t)r * DIM);
#pragma unroll
    for (int j = 0; j < 16; ++j) {
        float4 qv = q4[j];
        o4[j] = qv;
        float dx = qv.x - f[4 * j],     dy = qv.y - f[4 * j + 1];
        float dz = qv.z - f[4 * j + 2], dw = qv.w - f[4 * j + 3];
        dsum = fmaf(dx, dx, fmaf(dy, dy, fmaf(dz, dz, fmaf(dw, dw, dsum))));
    }
#pragma unroll
    for (int d = 0; d < DIM; ++d) atomicAdd(&g_esum[d * NEMB + bidx], f[d]);
    atomicAdd(&g_onehot[bidx], 1.f);
#pragma unroll
    for (int o = 16; o > 0; o >>= 1) dsum += __shfl_xor_sync(0xffffffffu, dsum, o);
    if (lane == 0) atomicAdd(&g_diffsum, dsum);
}

// ---------------- finalize: EMA buffers + scalar loss ----------------
__global__ void vq_fin(const float* __restrict__ cs, const float* __restrict__ ea,
                       float* __restrict__ out_diff, float* __restrict__ out_ncs,
                       float* __restrict__ out_nea, float* __restrict__ out_ne,
                       int nrows) {
    __shared__ float red[NEMB];
    const int t = threadIdx.x;

    float ncs = 0.99f * cs[t] + 0.01f * g_onehot[t];
    out_ncs[t] = ncs;

    red[t] = ncs;
    __syncthreads();
#pragma unroll
    for (int s = NEMB / 2; s > 0; s >>= 1) {
        if (t < s) red[t] += red[t + s];
        __syncthreads();
    }
    float n = red[0];
    float csn = (ncs + EPSF) / (n + (float)NEMB * EPSF) * n;

#pragma unroll
    for (int d = 0; d < DIM; ++d) {
        int i = d * NEMB + t;
        float nea = 0.99f * ea[i] + 0.01f * g_esum[i];
        out_nea[i] = nea;
        out_ne[i]  = nea / csn;
    }
    if (t == 0) out_diff[0] = g_diffsum / (float)((size_t)nrows * DIM);
}

// ---------------- launch ----------------
extern "C" void kernel_launch(void* const* d_in, const int* in_sizes, int n_in,
                              void* d_out, int out_size) {
    const float* x     = (const float*)d_in[0];
    const float* embed = (const float*)d_in[1];
    const float* cs    = (const float*)d_in[2];
    const float* ea    = (const float*)d_in[3];
    float* out = (float*)d_out;

    const int xsz = in_sizes[0];
    const int N   = xsz / DIM;

    float* out_q    = out;
    float* out_diff = out + xsz;
    float* out_ind  = out_diff + 1;
    float* out_ncs  = out_ind + N;
    float* out_nea  = out_ncs + NEMB;
    float* out_ne   = out_nea + DIM * NEMB;

    vq_split<<<(N * DIM / 4 + 255) / 256, 256>>>(x);
    vq_prep<<<(NEMB * DIM) / 256, 256>>>(embed);
    vq_main<<<N / MTILE, 128>>>(x, out_q, out_ind);
    vq_fin<<<1, NEMB>>>(cs, ea, out_diff, out_ncs, out_nea, out_ne, N);
}

// round 4
// speedup vs baseline: 3.0505x; 1.3795x over previous
#include <cuda_runtime.h>
#include <cuda_fp16.h>
#include <cstdint>

#define DIM      64
#define NEMB     1024
#define MTILE    128
#define NCH      64           // codes per chunk
#define NCHUNKS  (NEMB / NCH)
#define BROW     72           // padded B smem row stride in halves
#define EPSF     1e-5f

// ---------------- device scratch (static, no allocation) ----------------
__device__ __half g_eThi[NEMB * DIM];    // embed^T hi, [code][dim]
__device__ __half g_eTlo[NEMB * DIM];
__device__ float  g_eTf [NEMB * DIM];    // embed^T fp32 (gather + rescore)
__device__ float  g_enorm[NEMB];
__device__ float  g_onehot[NEMB];
__device__ float  g_esum[DIM * NEMB];
__device__ float  g_csn[NEMB];
__device__ float  g_diffsum;

// ---------------- PTX helpers ----------------
__device__ __forceinline__ uint32_t smem_u32(const void* p) {
    uint32_t a;
    asm("{ .reg .u64 t; cvta.to.shared.u64 t, %1; cvt.u32.u64 %0, t; }" : "=r"(a) : "l"(p));
    return a;
}
__device__ __forceinline__ void mma16816(float* d, const uint32_t* a, uint32_t b0, uint32_t b1) {
    asm volatile(
        "mma.sync.aligned.m16n8k16.row.col.f32.f16.f16.f32 "
        "{%0,%1,%2,%3}, {%4,%5,%6,%7}, {%8,%9}, {%0,%1,%2,%3};"
        : "+f"(d[0]), "+f"(d[1]), "+f"(d[2]), "+f"(d[3])
        : "r"(a[0]), "r"(a[1]), "r"(a[2]), "r"(a[3]), "r"(b0), "r"(b1));
}
#define CP16(dst, src) asm volatile("cp.async.cg.shared.global [%0], [%1], 16;" :: "r"(dst), "l"(src) : "memory")
#define CP_COMMIT()    asm volatile("cp.async.commit_group;" ::: "memory")
#define CP_WAIT(n)     asm volatile("cp.async.wait_group %0;" :: "n"(n) : "memory")

// ---------------- pre-pass: embed transpose/split + norms + zero stats ---
__global__ void vq_prep(const float* __restrict__ embed) {
    int i = blockIdx.x * blockDim.x + threadIdx.x;   // 65536 threads
    int d = i >> 10, n = i & (NEMB - 1);
    float e = embed[i];
    int t = n * DIM + d;
    g_eTf[t] = e;
    __half h = __float2half_rn(e);
    g_eThi[t] = h;
    g_eTlo[t] = __float2half_rn(e - __half2float(h));
    g_esum[i] = 0.f;
    if (i < NEMB) {
        g_onehot[i] = 0.f;
        float s = 0.f;
#pragma unroll
        for (int dd = 0; dd < DIM; ++dd) {
            float v = embed[dd * NEMB + i];
            s = fmaf(v, v, s);
        }
        g_enorm[i] = s;
    }
    if (i == 0) g_diffsum = 0.f;
}

// ---------------- main kernel ----------------
__global__ __launch_bounds__(128, 4)
void vq_main(const float* __restrict__ x, float* __restrict__ out_q,
             float* __restrict__ out_ind) {
    __shared__ __half sB[2][2][NCH * BROW];   // 36864 B; also A-staging overlay
    __shared__ float sEn[NEMB];               // 4 KB

    const int tid  = threadIdx.x;
    const int warp = tid >> 5;
    const int lane = tid & 31;
    const int g    = lane >> 2;
    const int q    = lane & 3;
    const int row0 = blockIdx.x * MTILE;

#pragma unroll
    for (int i = tid; i < NEMB; i += 128) sEn[i] = g_enorm[i];

    // ---- fused split: load x row, convert fp32 -> fp16 hi/lo into smem staging ----
    __half* sA  = &sB[0][0][0];               // [128][64] hi
    __half* sAl = sA + MTILE * DIM;           // [128][64] lo
    {
        const float4* xr = reinterpret_cast<const float4*>(x + (size_t)(row0 + tid) * DIM);
#pragma unroll
        for (int j = 0; j < 16; ++j) {
            float4 v = xr[j];
            __half h0 = __float2half_rn(v.x), h1 = __float2half_rn(v.y);
            __half h2 = __float2half_rn(v.z), h3 = __float2half_rn(v.w);
            __half l0 = __float2half_rn(v.x - __half2float(h0));
            __half l1 = __float2half_rn(v.y - __half2float(h1));
            __half l2 = __float2half_rn(v.z - __half2float(h2));
            __half l3 = __float2half_rn(v.w - __half2float(h3));
            *reinterpret_cast<__half2*>(sA  + tid * DIM + j * 4)     = __halves2half2(h0, h1);
            *reinterpret_cast<__half2*>(sA  + tid * DIM + j * 4 + 2) = __halves2half2(h2, h3);
            *reinterpret_cast<__half2*>(sAl + tid * DIM + j * 4)     = __halves2half2(l0, l1);
            *reinterpret_cast<__half2*>(sAl + tid * DIM + j * 4 + 2) = __halves2half2(l2, l3);
        }
    }
    __syncthreads();

    uint32_t Ah[2][4][4], Al[2][4][4];
    {
        const int c0 = q * 2;
#pragma unroll
        for (int mt = 0; mt < 2; ++mt) {
            const int ra = warp * 32 + mt * 16 + g;
            const int rb = ra + 8;
#pragma unroll
            for (int k = 0; k < 4; ++k) {
                const int cc = k * 16 + c0;
                Ah[mt][k][0] = *reinterpret_cast<const uint32_t*>(sA  + ra * DIM + cc);
                Ah[mt][k][1] = *reinterpret_cast<const uint32_t*>(sA  + rb * DIM + cc);
                Ah[mt][k][2] = *reinterpret_cast<const uint32_t*>(sA  + ra * DIM + cc + 8);
                Ah[mt][k][3] = *reinterpret_cast<const uint32_t*>(sA  + rb * DIM + cc + 8);
                Al[mt][k][0] = *reinterpret_cast<const uint32_t*>(sAl + ra * DIM + cc);
                Al[mt][k][1] = *reinterpret_cast<const uint32_t*>(sAl + rb * DIM + cc);
                Al[mt][k][2] = *reinterpret_cast<const uint32_t*>(sAl + ra * DIM + cc + 8);
                Al[mt][k][3] = *reinterpret_cast<const uint32_t*>(sAl + rb * DIM + cc + 8);
            }
        }
    }
    __syncthreads();   // staging region free for B buffers

    auto load_chunk = [&](int buf, int cb) {
#pragma unroll
        for (int i = tid; i < NCH * 8; i += 128) {
            int row = i >> 3, seg = i & 7;
            CP16(smem_u32(&sB[buf][0][row * BROW + seg * 8]),
                 g_eThi + (size_t)(cb + row) * DIM + seg * 8);
            CP16(smem_u32(&sB[buf][1][row * BROW + seg * 8]),
                 g_eTlo + (size_t)(cb + row) * DIM + seg * 8);
        }
    };

    float b1s[4], b2s[4];
    int   b1i[4], b2i[4];
#pragma unroll
    for (int rr = 0; rr < 4; ++rr) { b1s[rr] = b2s[rr] = 3.4e38f; b1i[rr] = b2i[rr] = 0; }

    load_chunk(0, 0);
    CP_COMMIT();

    for (int c = 0; c < NCHUNKS; ++c) {
        if (c < NCHUNKS - 1) {
            load_chunk((c + 1) & 1, (c + 1) * NCH);
            CP_COMMIT();
            CP_WAIT(1);
        } else {
            CP_WAIT(0);
        }
        __syncthreads();

        const __half* Bh = sB[c & 1][0];
        const __half* Bl = sB[c & 1][1];
        const int cb = c * NCH;

#pragma unroll
        for (int n = 0; n < 8; ++n) {
            // B fragments for this n: hi and lo, all 4 k-steps (pass 2 reuses hi frags)
            uint32_t bh0[4], bh1[4], bl0[4], bl1[4];
#pragma unroll
            for (int k = 0; k < 4; ++k) {
                const __half* ph = Bh + (n * 8 + g) * BROW + k * 16 + q * 2;
                const __half* pl = Bl + (n * 8 + g) * BROW + k * 16 + q * 2;
                bh0[k] = *reinterpret_cast<const uint32_t*>(ph);
                bh1[k] = *reinterpret_cast<const uint32_t*>(ph + 8);
                bl0[k] = *reinterpret_cast<const uint32_t*>(pl);
                bl1[k] = *reinterpret_cast<const uint32_t*>(pl + 8);
            }
            float acc[2][4];
#pragma unroll
            for (int mt = 0; mt < 2; ++mt)
#pragma unroll
                for (int v = 0; v < 4; ++v) acc[mt][v] = 0.f;

#pragma unroll
            for (int k = 0; k < 4; ++k) {       // hi * hi
                mma16816(acc[0], Ah[0][k], bh0[k], bh1[k]);
                mma16816(acc[1], Ah[1][k], bh0[k], bh1[k]);
            }
#pragma unroll
            for (int k = 0; k < 4; ++k) {       // hi * lo
                mma16816(acc[0], Ah[0][k], bl0[k], bl1[k]);
                mma16816(acc[1], Ah[1][k], bl0[k], bl1[k]);
            }
#pragma unroll
            for (int k = 0; k < 4; ++k) {       // lo * hi
                mma16816(acc[0], Al[0][k], bh0[k], bh1[k]);
                mma16816(acc[1], Al[1][k], bh0[k], bh1[k]);
            }

            const int code0 = cb + n * 8 + q * 2;
            const float en0 = sEn[code0], en1 = sEn[code0 + 1];
#pragma unroll
            for (int mt = 0; mt < 2; ++mt) {
#pragma unroll
                for (int h = 0; h < 2; ++h) {
                    const int rr = mt * 2 + h;
                    float s0 = fmaf(-2.f, acc[mt][h * 2],     en0);
                    float s1 = fmaf(-2.f, acc[mt][h * 2 + 1], en1);
                    if (s0 < b1s[rr]) { b2s[rr] = b1s[rr]; b2i[rr] = b1i[rr]; b1s[rr] = s0; b1i[rr] = code0; }
                    else if (s0 < b2s[rr]) { b2s[rr] = s0; b2i[rr] = code0; }
                    if (s1 < b1s[rr]) { b2s[rr] = b1s[rr]; b2i[rr] = b1i[rr]; b1s[rr] = s1; b1i[rr] = code0 + 1; }
                    else if (s1 < b2s[rr]) { b2s[rr] = s1; b2i[rr] = code0 + 1; }
                }
            }
        }
        __syncthreads();
    }

    // ---- cross-lane top-2 merge (4 lanes per row group) ----
#pragma unroll
    for (int off = 1; off <= 2; off <<= 1) {
#pragma unroll
        for (int rr = 0; rr < 4; ++rr) {
            float o1s = __shfl_xor_sync(0xffffffffu, b1s[rr], off);
            int   o1i = __shfl_xor_sync(0xffffffffu, b1i[rr], off);
            float o2s = __shfl_xor_sync(0xffffffffu, b2s[rr], off);
            int   o2i = __shfl_xor_sync(0xffffffffu, b2i[rr], off);
            bool ob = (o1s < b1s[rr]) || (o1s == b1s[rr] && o1i < b1i[rr]);
            float n1s, n2s; int n1i, n2i;
            if (ob) {
                n1s = o1s; n1i = o1i;
                if (b1s[rr] < o2s || (b1s[rr] == o2s && b1i[rr] < o2i)) { n2s = b1s[rr]; n2i = b1i[rr]; }
                else                                                    { n2s = o2s;     n2i = o2i; }
            } else {
                n1s = b1s[rr]; n1i = b1i[rr];
                if (o1s < b2s[rr] || (o1s == b2s[rr] && o1i < b2i[rr])) { n2s = o1s;     n2i = o1i; }
                else                                                    { n2s = b2s[rr]; n2i = b2i[rr]; }
            }
            b1s[rr] = n1s; b1i[rr] = n1i; b2s[rr] = n2s; b2i[rr] = n2i;
        }
    }

    // ---- publish per-row candidates (overlay on sB) ----
    float* rs1 = reinterpret_cast<float*>(&sB[0][0][0]);
    int*   ri1 = reinterpret_cast<int*>(rs1 + MTILE);
    float* rs2 = rs1 + 2 * MTILE;
    int*   ri2 = reinterpret_cast<int*>(rs1 + 3 * MTILE);
    if (q == 0) {
#pragma unroll
        for (int rr = 0; rr < 4; ++rr) {
            int rl = warp * 32 + (rr >> 1) * 16 + (rr & 1) * 8 + g;
            rs1[rl] = b1s[rr]; ri1[rl] = b1i[rr];
            rs2[rl] = b2s[rr]; ri2[rl] = b2i[rr];
        }
    }
    __syncthreads();

    // ---- epilogue: one thread per row ----
    const int r = row0 + tid;
    float f[DIM];
    {
        const float4* xr = reinterpret_cast<const float4*>(x + (size_t)r * DIM);
#pragma unroll
        for (int j = 0; j < 16; ++j) {
            float4 v = xr[j];
            f[4 * j] = v.x; f[4 * j + 1] = v.y; f[4 * j + 2] = v.z; f[4 * j + 3] = v.w;
        }
    }
    int bidx = ri1[tid];
    if (rs2[tid] - rs1[tid] < 5e-3f) {   // near-tie rescue: exact fp32 rescore
        int i2 = ri2[tid];
        float d1 = 0.f, d2 = 0.f;
        const float* e1 = g_eTf + bidx * DIM;
        const float* e2 = g_eTf + i2 * DIM;
#pragma unroll
        for (int d = 0; d < DIM; ++d) {
            d1 = fmaf(f[d], e1[d], d1);
            d2 = fmaf(f[d], e2[d], d2);
        }
        float s1 = g_enorm[bidx] - 2.f * d1;
        float s2 = g_enorm[i2]   - 2.f * d2;
        if (s2 < s1 || (s2 == s1 && i2 < bidx)) bidx = i2;
    }
    out_ind[r] = (float)bidx;

    float dsum = 0.f;
    const float4* q4 = reinterpret_cast<const float4*>(g_eTf + bidx * DIM);
    float4* o4 = reinterpret_cast<float4*>(out_q + (size_t)r * DIM);
#pragma unroll
    for (int j = 0; j < 16; ++j) {
        float4 qv = q4[j];
        o4[j] = qv;
        float dx = qv.x - f[4 * j],     dy = qv.y - f[4 * j + 1];
        float dz = qv.z - f[4 * j + 2], dw = qv.w - f[4 * j + 3];
        dsum = fmaf(dx, dx, fmaf(dy, dy, fmaf(dz, dz, fmaf(dw, dw, dsum))));
    }
#pragma unroll
    for (int d = 0; d < DIM; ++d) atomicAdd(&g_esum[d * NEMB + bidx], f[d]);
    atomicAdd(&g_onehot[bidx], 1.f);
#pragma unroll
    for (int o = 16; o > 0; o >>= 1) dsum += __shfl_xor_sync(0xffffffffu, dsum, o);
    if (lane == 0) atomicAdd(&g_diffsum, dsum);
}

// ---------------- fin1: cluster-size EMA + normalization factor ----------
__global__ void vq_fin1(const float* __restrict__ cs, float* __restrict__ out_ncs) {
    __shared__ float red[NEMB];
    const int t = threadIdx.x;
    float ncs = 0.99f * cs[t] + 0.01f * g_onehot[t];
    out_ncs[t] = ncs;
    red[t] = ncs;
    __syncthreads();
#pragma unroll
    for (int s = NEMB / 2; s > 0; s >>= 1) {
        if (t < s) red[t] += red[t + s];
        __syncthreads();
    }
    float n = red[0];
    g_csn[t] = (ncs + EPSF) / (n + (float)NEMB * EPSF) * n;
}

// ---------------- fin2: embed-avg EMA + new embed + scalar loss ----------
__global__ void vq_fin2(const float* __restrict__ ea, float* __restrict__ out_diff,
                        float* __restrict__ out_nea, float* __restrict__ out_ne,
                        int nrows) {
    int i = blockIdx.x * blockDim.x + threadIdx.x;   // 65536 threads
    float nea = 0.99f * ea[i] + 0.01f * g_esum[i];
    out_nea[i] = nea;
    out_ne[i]  = nea / g_csn[i & (NEMB - 1)];
    if (i == 0) out_diff[0] = g_diffsum / (float)((size_t)nrows * DIM);
}

// ---------------- launch ----------------
extern "C" void kernel_launch(void* const* d_in, const int* in_sizes, int n_in,
                              void* d_out, int out_size) {
    const float* x     = (const float*)d_in[0];
    const float* embed = (const float*)d_in[1];
    const float* cs    = (const float*)d_in[2];
    const float* ea    = (const float*)d_in[3];
    float* out = (float*)d_out;

    const int xsz = in_sizes[0];
    const int N   = xsz / DIM;

    float* out_q    = out;
    float* out_diff = out + xsz;
    float* out_ind  = out_diff + 1;
    float* out_ncs  = out_ind + N;
    float* out_nea  = out_ncs + NEMB;
    float* out_ne   = out_nea + DIM * NEMB;

    vq_prep<<<(NEMB * DIM) / 256, 256>>>(embed);
    vq_main<<<N / MTILE, 128>>>(x, out_q, out_ind);
    vq_fin1<<<1, NEMB>>>(cs, out_ncs);
    vq_fin2<<<(NEMB * DIM) / 256, 256>>>(ea, out_diff, out_nea, out_ne, N);
}

// round 6
// speedup vs baseline: 5.0682x; 1.6614x over previous
#include <cuda_runtime.h>
#include <cuda_fp16.h>
#include <cstdint>

#define DIM      64
#define NEMB     1024
#define MTILE    128
#define NCH      64           // codes per chunk
#define NCHUNKS  (NEMB / NCH)
#define BROW     72           // padded B smem row stride in halves
#define EPSF     1e-5f
#define THETA    0.125f       // exact-rescore margin

// ---------------- device scratch ----------------
__device__ __half g_eThi[NEMB * DIM];    // embed^T hi, [code][dim]
__device__ float  g_eTf [NEMB * DIM];    // embed^T fp32 (gather + rescore)
__device__ float  g_enorm[NEMB];
__device__ float  g_onehot[NEMB];
__device__ float  g_esum[DIM * NEMB];
__device__ float  g_csn[NEMB];
__device__ float  g_diffsum;

// ---------------- PTX helpers ----------------
__device__ __forceinline__ uint32_t smem_u32(const void* p) {
    uint32_t a;
    asm("{ .reg .u64 t; cvta.to.shared.u64 t, %1; cvt.u32.u64 %0, t; }" : "=r"(a) : "l"(p));
    return a;
}
__device__ __forceinline__ void mma16816(float* d, const uint32_t* a, uint32_t b0, uint32_t b1) {
    asm volatile(
        "mma.sync.aligned.m16n8k16.row.col.f32.f16.f16.f32 "
        "{%0,%1,%2,%3}, {%4,%5,%6,%7}, {%8,%9}, {%0,%1,%2,%3};"
        : "+f"(d[0]), "+f"(d[1]), "+f"(d[2]), "+f"(d[3])
        : "r"(a[0]), "r"(a[1]), "r"(a[2]), "r"(a[3]), "r"(b0), "r"(b1));
}
#define CP16(dst, src) asm volatile("cp.async.cg.shared.global [%0], [%1], 16;" :: "r"(dst), "l"(src) : "memory")
#define CP_COMMIT()    asm volatile("cp.async.commit_group;" ::: "memory")
#define CP_WAIT(n)     asm volatile("cp.async.wait_group %0;" :: "n"(n) : "memory")

// ordered-uint key: monotone in score, code in low 10 bits
__device__ __forceinline__ uint32_t okey(float s, uint32_t code) {
    uint32_t b = __float_as_uint(s);
    b ^= (uint32_t)((int32_t)b >> 31) | 0x80000000u;
    return (b & 0xFFFFFC00u) | code;
}
__device__ __forceinline__ float okey_dec(uint32_t k) {
    uint32_t o = k & 0xFFFFFC00u;
    uint32_t m = (uint32_t)((int32_t)(~o) >> 31) | 0x80000000u;
    return __uint_as_float(o ^ m);
}
__device__ __forceinline__ void ins3(uint32_t& b1, uint32_t& b2, uint32_t& b3, uint32_t k) {
    uint32_t h1 = max(b1, k); b1 = min(b1, k);
    uint32_t h2 = max(b2, h1); b2 = min(b2, h1);
    b3 = min(b3, h2);
}

// ---------------- pre-pass: embed transpose/split + norms + zero stats ---
__global__ void vq_prep(const float* __restrict__ embed) {
    int i = blockIdx.x * blockDim.x + threadIdx.x;   // 65536 threads
    int d = i >> 10, n = i & (NEMB - 1);
    float e = embed[i];
    int t = n * DIM + d;
    g_eTf[t] = e;
    g_eThi[t] = __float2half_rn(e);
    g_esum[i] = 0.f;
    if (i < NEMB) {
        g_onehot[i] = 0.f;
        float s = 0.f;
#pragma unroll
        for (int dd = 0; dd < DIM; ++dd) {
            float v = embed[dd * NEMB + i];
            s = fmaf(v, v, s);
        }
        g_enorm[i] = s;
    }
    if (i == 0) g_diffsum = 0.f;
}

// ---------------- main kernel ----------------
__global__ __launch_bounds__(128, 4)
void vq_main(const float* __restrict__ x, float* __restrict__ out_q,
             float* __restrict__ out_ind) {
    __shared__ __half sB[2][NCH * BROW];          // 2 x 9216 B (hi only); A-staging + cand overlay
    __shared__ __align__(8) float sEn[NEMB];      // 4 KB

    const int tid  = threadIdx.x;
    const int warp = tid >> 5;
    const int lane = tid & 31;
    const int g    = lane >> 2;
    const int q    = lane & 3;
    const int row0 = blockIdx.x * MTILE;

#pragma unroll
    for (int i = tid; i < NEMB; i += 128) sEn[i] = g_enorm[i];

    // ---- fused split: x row -> fp16 hi into smem staging ----
    __half* sA = &sB[0][0];                        // [128][64] = 16 KB (fits 18.4 KB)
    {
        const float4* xr = reinterpret_cast<const float4*>(x + (size_t)(row0 + tid) * DIM);
#pragma unroll
        for (int j = 0; j < 16; ++j) {
            float4 v = xr[j];
            *reinterpret_cast<__half2*>(sA + tid * DIM + j * 4) =
                __halves2half2(__float2half_rn(v.x), __float2half_rn(v.y));
            *reinterpret_cast<__half2*>(sA + tid * DIM + j * 4 + 2) =
                __halves2half2(__float2half_rn(v.z), __float2half_rn(v.w));
        }
    }
    __syncthreads();

    uint32_t Ah[2][4][4];
    {
        const int c0 = q * 2;
#pragma unroll
        for (int mt = 0; mt < 2; ++mt) {
            const int ra = warp * 32 + mt * 16 + g;
            const int rb = ra + 8;
#pragma unroll
            for (int k = 0; k < 4; ++k) {
                const int cc = k * 16 + c0;
                Ah[mt][k][0] = *reinterpret_cast<const uint32_t*>(sA + ra * DIM + cc);
                Ah[mt][k][1] = *reinterpret_cast<const uint32_t*>(sA + rb * DIM + cc);
                Ah[mt][k][2] = *reinterpret_cast<const uint32_t*>(sA + ra * DIM + cc + 8);
                Ah[mt][k][3] = *reinterpret_cast<const uint32_t*>(sA + rb * DIM + cc + 8);
            }
        }
    }
    __syncthreads();   // staging region free for B buffers

    auto load_chunk = [&](int buf, int cb) {
#pragma unroll
        for (int i = tid; i < NCH * 8; i += 128) {     // 512 16B segs
            int row = i >> 3, seg = i & 7;
            CP16(smem_u32(&sB[buf][row * BROW + seg * 8]),
                 g_eThi + (size_t)(cb + row) * DIM + seg * 8);
        }
    };

    // per-lane top-3 packed keys for each of the 4 row-slots
    uint32_t k1[4], k2[4], k3[4];
#pragma unroll
    for (int rr = 0; rr < 4; ++rr) { k1[rr] = k2[rr] = k3[rr] = 0xFFFFFFFFu; }

    load_chunk(0, 0);
    CP_COMMIT();

    for (int c = 0; c < NCHUNKS; ++c) {
        if (c < NCHUNKS - 1) {
            load_chunk((c + 1) & 1, (c + 1) * NCH);
            CP_COMMIT();
            CP_WAIT(1);
        } else {
            CP_WAIT(0);
        }
        __syncthreads();

        const __half* Bh = sB[c & 1];
        const int cb = c * NCH;

#pragma unroll
        for (int n = 0; n < 8; ++n) {
            uint32_t b0[4], b1[4];
#pragma unroll
            for (int k = 0; k < 4; ++k) {
                const __half* p = Bh + (n * 8 + g) * BROW + k * 16 + q * 2;
                b0[k] = *reinterpret_cast<const uint32_t*>(p);
                b1[k] = *reinterpret_cast<const uint32_t*>(p + 8);
            }
            float acc[2][4];
#pragma unroll
            for (int mt = 0; mt < 2; ++mt)
#pragma unroll
                for (int v = 0; v < 4; ++v) acc[mt][v] = 0.f;
#pragma unroll
            for (int k = 0; k < 4; ++k) {
                mma16816(acc[0], Ah[0][k], b0[k], b1[k]);
                mma16816(acc[1], Ah[1][k], b0[k], b1[k]);
            }

            const uint32_t code0 = (uint32_t)(cb + n * 8 + q * 2);
            const float2 en2 = *reinterpret_cast<const float2*>(&sEn[code0]);
#pragma unroll
            for (int mt = 0; mt < 2; ++mt) {
#pragma unroll
                for (int h = 0; h < 2; ++h) {
                    const int rr = mt * 2 + h;
                    float s0 = fmaf(-2.f, acc[mt][h * 2],     en2.x);
                    float s1 = fmaf(-2.f, acc[mt][h * 2 + 1], en2.y);
                    ins3(k1[rr], k2[rr], k3[rr], okey(s0, code0));
                    ins3(k1[rr], k2[rr], k3[rr], okey(s1, code0 + 1));
                }
            }
        }
        __syncthreads();
    }

    // ---- publish candidates: 4 lanes x top-3 = 12 per row (overlay on sB) ----
    uint32_t* sCand = reinterpret_cast<uint32_t*>(&sB[0][0]);   // [128][12] = 6 KB
#pragma unroll
    for (int rr = 0; rr < 4; ++rr) {
        int rl = warp * 32 + (rr >> 1) * 16 + (rr & 1) * 8 + g;
        sCand[rl * 12 + q * 3 + 0] = k1[rr];
        sCand[rl * 12 + q * 3 + 1] = k2[rr];
        sCand[rl * 12 + q * 3 + 2] = k3[rr];
    }
    __syncthreads();

    // ---- epilogue: one thread per row ----
    const int r = row0 + tid;
    float f[DIM];
    {
        const float4* xr = reinterpret_cast<const float4*>(x + (size_t)r * DIM);
#pragma unroll
        for (int j = 0; j < 16; ++j) {
            float4 v = xr[j];
            f[4 * j] = v.x; f[4 * j + 1] = v.y; f[4 * j + 2] = v.z; f[4 * j + 3] = v.w;
        }
    }

    uint32_t keys[12];
    uint32_t kmin = 0xFFFFFFFFu;
#pragma unroll
    for (int j = 0; j < 12; ++j) { keys[j] = sCand[tid * 12 + j]; kmin = min(kmin, keys[j]); }
    float smin = okey_dec(kmin);
    int bidx = (int)(kmin & 1023u);

    int nclose = 0;
#pragma unroll
    for (int j = 0; j < 12; ++j) nclose += (okey_dec(keys[j]) - smin < THETA) ? 1 : 0;

    if (nclose > 1) {   // ambiguous: exact fp32 rescore of close candidates
        float bs = 3.4e38f;
        int bi = NEMB;
#pragma unroll 4
        for (int j = 0; j < 12; ++j) {
            if (okey_dec(keys[j]) - smin < THETA) {
                int cc = (int)(keys[j] & 1023u);
                const float* e = g_eTf + cc * DIM;
                float a0 = 0.f, a1 = 0.f, a2 = 0.f, a3 = 0.f;
#pragma unroll
                for (int d = 0; d < DIM; d += 4) {
                    a0 = fmaf(f[d],     e[d],     a0);
                    a1 = fmaf(f[d + 1], e[d + 1], a1);
                    a2 = fmaf(f[d + 2], e[d + 2], a2);
                    a3 = fmaf(f[d + 3], e[d + 3], a3);
                }
                float s = sEn[cc] - 2.f * ((a0 + a1) + (a2 + a3));
                if (s < bs || (s == bs && cc < bi)) { bs = s; bi = cc; }
            }
        }
        bidx = bi;
    }
    out_ind[r] = (float)bidx;

    float dsum = 0.f;
    const float4* q4 = reinterpret_cast<const float4*>(g_eTf + bidx * DIM);
    float4* o4 = reinterpret_cast<float4*>(out_q + (size_t)r * DIM);
#pragma unroll
    for (int j = 0; j < 16; ++j) {
        float4 qv = q4[j];
        o4[j] = qv;
        float dx = qv.x - f[4 * j],     dy = qv.y - f[4 * j + 1];
        float dz = qv.z - f[4 * j + 2], dw = qv.w - f[4 * j + 3];
        dsum = fmaf(dx, dx, fmaf(dy, dy, fmaf(dz, dz, fmaf(dw, dw, dsum))));
    }
#pragma unroll
    for (int d = 0; d < DIM; ++d) atomicAdd(&g_esum[d * NEMB + bidx], f[d]);
    atomicAdd(&g_onehot[bidx], 1.f);
#pragma unroll
    for (int o = 16; o > 0; o >>= 1) dsum += __shfl_xor_sync(0xffffffffu, dsum, o);
    if (lane == 0) atomicAdd(&g_diffsum, dsum);
}

// ---------------- fin1: cluster-size EMA + normalization factor ----------
__global__ void vq_fin1(const float* __restrict__ cs, float* __restrict__ out_ncs) {
    __shared__ float red[NEMB];
    const int t = threadIdx.x;
    float ncs = 0.99f * cs[t] + 0.01f * g_onehot[t];
    out_ncs[t] = ncs;
    red[t] = ncs;
    __syncthreads();
#pragma unroll
    for (int s = NEMB / 2; s > 0; s >>= 1) {
        if (t < s) red[t] += red[t + s];
        __syncthreads();
    }
    float n = red[0];
    g_csn[t] = (ncs + EPSF) / (n + (float)NEMB * EPSF) * n;
}

// ---------------- fin2: embed-avg EMA + new embed + scalar loss ----------
__global__ void vq_fin2(const float* __restrict__ ea, float* __restrict__ out_diff,
                        float* __restrict__ out_nea, float* __restrict__ out_ne,
                        int nrows) {
    int i = blockIdx.x * blockDim.x + threadIdx.x;   // 65536 threads
    float nea = 0.99f * ea[i] + 0.01f * g_esum[i];
    out_nea[i] = nea;
    out_ne[i]  = nea / g_csn[i & (NEMB - 1)];
    if (i == 0) out_diff[0] = g_diffsum / (float)((size_t)nrows * DIM);
}

// ---------------- launch ----------------
extern "C" void kernel_launch(void* const* d_in, const int* in_sizes, int n_in,
                              void* d_out, int out_size) {
    const float* x     = (const float*)d_in[0];
    const float* embed = (const float*)d_in[1];
    const float* cs    = (const float*)d_in[2];
    const float* ea    = (const float*)d_in[3];
    float* out = (float*)d_out;

    const int xsz = in_sizes[0];
    const int N   = xsz / DIM;

    float* out_q    = out;
    float* out_diff = out + xsz;
    float* out_ind  = out_diff + 1;
    float* out_ncs  = out_ind + N;
    float* out_nea  = out_ncs + NEMB;
    float* out_ne   = out_nea + DIM * NEMB;

    vq_prep<<<(NEMB * DIM) / 256, 256>>>(embed);
    vq_main<<<N / MTILE, 128>>>(x, out_q, out_ind);
    vq_fin1<<<1, NEMB>>>(cs, out_ncs);
    vq_fin2<<<(NEMB * DIM) / 256, 256>>>(ea, out_diff, out_nea, out_ne, N);
}